// round 14
// baseline (speedup 1.0000x reference)
#include <cuda_runtime.h>
#include <cuda_bf16.h>
#include <math.h>
#include <stdint.h>

#define Bb 128
#define Ss 256
#define Ii 512
#define Oo 512
#define Hh 1024
#define Gg (3*Hh)      // 3072
#define IOio (Ii+Oo)   // 1024

// ---- output layout ----
#define PROBS_OFF  0
#define PRE_OFF    ((size_t)Bb*Ss*Oo)
#define SAMP_OFF   (PRE_OFF + (size_t)Bb*Ss*Hh)
#define HX_OFF     (SAMP_OFF + (size_t)Bb*Ss*Oo)

// ---- scratch ----
__device__ int   g_idx[Bb*Ss];
__device__ float g_gi[(size_t)Ss*Bb*Gg];
__device__ float g_h[Bb*Hh];
__device__ float g_ghp[3][(size_t)Bb*Gg];
__device__ float g_logits[(size_t)Bb*Ss*Oo];
// bf16 3-way splits (recurrence, unchanged)
__device__ __nv_bfloat16 g_h1[Bb*Hh];
__device__ __nv_bfloat16 g_h2[Bb*Hh];
__device__ __nv_bfloat16 g_h3[Bb*Hh];
__device__ __nv_bfloat16 g_w1[(size_t)Gg*Hh];
__device__ __nv_bfloat16 g_w2[(size_t)Gg*Hh];
__device__ __nv_bfloat16 g_w3[(size_t)Gg*Hh];
// tf32 2-way splits (gi + logits GEMMs)
__device__ float g_ya[(size_t)Bb*Ss*Ii];
__device__ float g_yb[(size_t)Bb*Ss*Ii];
__device__ float g_wa[(size_t)Gg*Ii];
__device__ float g_wb[(size_t)Gg*Ii];
__device__ float g_hsa[(size_t)Bb*Ss*Hh];
__device__ float g_hsb[(size_t)Bb*Ss*Hh];
__device__ float g_lwa[(size_t)Oo*Hh];
__device__ float g_lwb[(size_t)Oo*Hh];

// bf16 recurrence product table: seg -> (A split idx, B split idx)
__constant__ int SEG_A[6] = {0,0,1,0,2,1};
__constant__ int SEG_B[6] = {0,1,0,2,0,1};

// ============================================================
// PTX helpers
// ============================================================
__device__ __forceinline__ uint32_t smem_u32(const void* p) {
    uint32_t a;
    asm("{ .reg .u64 t; cvta.to.shared.u64 t, %1; cvt.u32.u64 %0, t; }" : "=r"(a) : "l"(p));
    return a;
}
__device__ __forceinline__ void cp16(uint32_t dst, const void* src) {
    asm volatile("cp.async.cg.shared.global [%0], [%1], 16;" :: "r"(dst), "l"(src));
}
#define CP_COMMIT() asm volatile("cp.async.commit_group;" ::: "memory")
#define CP_WAIT(n)  asm volatile("cp.async.wait_group %0;" :: "n"(n) : "memory")

__device__ __forceinline__ uint32_t lds32(uint32_t addr) {
    uint32_t v;
    asm volatile("ld.shared.b32 %0, [%1];" : "=r"(v) : "r"(addr));
    return v;
}
__device__ __forceinline__ void ldmA(uint32_t* a, uint32_t addr) {
    asm volatile("ldmatrix.sync.aligned.m8n8.x4.shared.b16 {%0,%1,%2,%3}, [%4];"
        : "=r"(a[0]), "=r"(a[1]), "=r"(a[2]), "=r"(a[3]) : "r"(addr));
}
__device__ __forceinline__ void ldmB4(uint32_t* b, uint32_t addr) {
    asm volatile("ldmatrix.sync.aligned.m8n8.x4.shared.b16 {%0,%1,%2,%3}, [%4];"
        : "=r"(b[0]), "=r"(b[1]), "=r"(b[2]), "=r"(b[3]) : "r"(addr));
}
__device__ __forceinline__ void mma_bf16(float* c, const uint32_t* a, const uint32_t* b) {
    asm volatile("mma.sync.aligned.m16n8k16.row.col.f32.bf16.bf16.f32 "
        "{%0,%1,%2,%3}, {%4,%5,%6,%7}, {%8,%9}, {%0,%1,%2,%3};"
        : "+f"(c[0]), "+f"(c[1]), "+f"(c[2]), "+f"(c[3])
        : "r"(a[0]), "r"(a[1]), "r"(a[2]), "r"(a[3]), "r"(b[0]), "r"(b[1]));
}
__device__ __forceinline__ void mma_tf32(float* c, const uint32_t* a, const uint32_t* b) {
    asm volatile("mma.sync.aligned.m16n8k8.row.col.f32.tf32.tf32.f32 "
        "{%0,%1,%2,%3}, {%4,%5,%6,%7}, {%8,%9}, {%0,%1,%2,%3};"
        : "+f"(c[0]), "+f"(c[1]), "+f"(c[2]), "+f"(c[3])
        : "r"(a[0]), "r"(a[1]), "r"(a[2]), "r"(a[3]), "r"(b[0]), "r"(b[1]));
}
__device__ __forceinline__ float tf32_rna(float v) {
    uint32_t r;
    asm("cvt.rna.tf32.f32 %0, %1;" : "=r"(r) : "f"(v));
    return __uint_as_float(r);
}

// ---- bf16 step-GEMM pipeline constants (R13, unchanged) ----
#define STRD 80
#define STAGE_BYTES ((128+64)*STRD)  // 15360
#define NBUF 6

// bf16 chunk compute: warp tile 32x32 (4M x 2N). Identical to R13.
__device__ __forceinline__ void compute_chunk(uint32_t aB, uint32_t bB, int wm, int wn,
                                              int lane, float acc[2][4][4]) {
    uint32_t a[2][2][4], b[2][2][4];
    int t = lane >> 3, r = lane & 7;
    #pragma unroll
    for (int kk = 0; kk < 2; kk++) {
        #pragma unroll
        for (int mt = 0; mt < 2; mt++)
            ldmA(a[kk][mt], aB + (wm + mt*16 + (lane & 15))*STRD + kk*32 + ((lane >> 4) & 1)*16);
        #pragma unroll
        for (int ldi = 0; ldi < 2; ldi++)
            ldmB4(b[kk][ldi], bB + (wn + ldi*16 + (t >> 1)*8 + r)*STRD + kk*32 + (t & 1)*16);
    }
    #pragma unroll
    for (int kk = 0; kk < 2; kk++)
        #pragma unroll
        for (int mt = 0; mt < 2; mt++)
            #pragma unroll
            for (int nt = 0; nt < 4; nt++)
                mma_bf16(acc[mt][nt], a[kk][mt], &b[kk][nt >> 1][(nt & 1)*2]);
}

// ---- tf32 pipeline constants (gi + logits) ----
#define STRD2 80                       // 16 floats (64B) + 16B pad -> conflict-free
#define STAGE2 ((128+64)*STRD2)        // 15360
#define NBUF2 6

// tf32 chunk compute: BK=16 (2 x k8), warp tile 32x32 (2 m-tiles x 4 n-tiles)
__device__ __forceinline__ void compute_chunk_tf(uint32_t aB, uint32_t bB, int wm, int wn,
                                                 int lane, float acc[2][4][4]) {
    int r4 = lane >> 2, c4 = lane & 3;
    uint32_t a[2][2][4], b[2][4][2];
    #pragma unroll
    for (int kk = 0; kk < 2; kk++) {
        #pragma unroll
        for (int mt = 0; mt < 2; mt++) {
            uint32_t base = aB + (wm + mt*16 + r4)*STRD2 + (kk*8 + c4)*4;
            a[kk][mt][0] = lds32(base);
            a[kk][mt][1] = lds32(base + 8*STRD2);
            a[kk][mt][2] = lds32(base + 16);
            a[kk][mt][3] = lds32(base + 8*STRD2 + 16);
        }
        #pragma unroll
        for (int nt = 0; nt < 4; nt++) {
            uint32_t nb = bB + (wn + nt*8 + r4)*STRD2 + (kk*8 + c4)*4;
            b[kk][nt][0] = lds32(nb);
            b[kk][nt][1] = lds32(nb + 16);
        }
    }
    #pragma unroll
    for (int kk = 0; kk < 2; kk++)
        #pragma unroll
        for (int mt = 0; mt < 2; mt++)
            #pragma unroll
            for (int nt = 0; nt < 4; nt++)
                mma_tf32(acc[mt][nt], a[kk][mt], b[kk][nt]);
}

// ============================================================
// prep kernels
// ============================================================
__global__ void k_idx(const float* __restrict__ gt, const float* __restrict__ gotoken) {
    int wg   = (blockIdx.x * blockDim.x + threadIdx.x) >> 5;
    int lane = threadIdx.x & 31;
    if (wg >= Bb*Ss) return;
    int s = wg / Bb, b = wg % Bb;
    const float* src = (s == 0) ? gotoken : (gt + ((size_t)b*Ss + (s-1))*Oo);
    int found = Oo;
    for (int o = lane; o < Oo; o += 32)
        if (src[o] > 0.5f) found = min(found, o);
    #pragma unroll
    for (int off = 16; off; off >>= 1)
        found = min(found, __shfl_xor_sync(0xffffffffu, found, off));
    if (lane == 0) g_idx[wg] = found;
}

__device__ __forceinline__ void split3(float v, __nv_bfloat16& a, __nv_bfloat16& b, __nv_bfloat16& c) {
    a = __float2bfloat16(v);
    float r = v - __bfloat162float(a);
    b = __float2bfloat16(r);
    c = __float2bfloat16(r - __bfloat162float(b));
}

__global__ void k_copyh(const float* __restrict__ hx) {
    int i = blockIdx.x * blockDim.x + threadIdx.x;
    if (i < Bb*Hh) {
        float v = hx[i];
        g_h[i] = v;
        split3(v, g_h1[i], g_h2[i], g_h3[i]);
    }
}
__global__ void k_split_w(const float* __restrict__ w) {
    int i = blockIdx.x * blockDim.x + threadIdx.x;
    if (i < Gg*Hh) split3(w[i], g_w1[i], g_w2[i], g_w3[i]);
}
__global__ void k_split2_y(const float* __restrict__ y) {
    int i = blockIdx.x * blockDim.x + threadIdx.x;
    if (i < Bb*Ss*Ii) {
        float v = y[i];
        float t1 = tf32_rna(v);
        g_ya[i] = t1;
        g_yb[i] = tf32_rna(v - t1);
    }
}
__global__ void k_split2_wiy(const float* __restrict__ wih) {
    int i = blockIdx.x * blockDim.x + threadIdx.x;
    if (i < Gg*Ii) {
        int row = i / Ii, col = i % Ii;
        float v = wih[(size_t)row*IOio + col];
        float t1 = tf32_rna(v);
        g_wa[i] = t1;
        g_wb[i] = tf32_rna(v - t1);
    }
}
__global__ void k_split2_lw(const float* __restrict__ lw) {
    int i = blockIdx.x * blockDim.x + threadIdx.x;
    if (i < Oo*Hh) {
        float v = lw[i];
        float t1 = tf32_rna(v);
        g_lwa[i] = t1;
        g_lwb[i] = tf32_rna(v - t1);
    }
}

// ============================================================
// 2) gi GEMM via tf32 3-product: per-s tile 128x3072, K'=3x512
//    grid (48, 256); 96 chunks of BK=16; paired pipeline.
//    Product order (noise-minimizing): (y1,w2), (y2,w1), (y1,w1)
// ============================================================
__global__ __launch_bounds__(256) void k_gemm_gi_tf(const float* __restrict__ wih,
                                                    const float* __restrict__ bih) {
    extern __shared__ __align__(16) char dyn[];
    int tid = threadIdx.x, wid = tid >> 5, lane = tid & 31;
    int n0 = blockIdx.x * 64;
    int s  = blockIdx.y;
    int wm = (wid >> 1) * 32, wn = (wid & 1) * 32;
    uint32_t sb = smem_u32(dyn);
    const float* Asrc[3] = { g_ya, g_yb, g_ya };
    const float* Bsrc[3] = { g_wb, g_wa, g_wa };

    auto issue = [&](int c) {
        uint32_t aBuf = sb + (c % NBUF2)*STAGE2;
        uint32_t bBuf = aBuf + 128*STRD2;
        int seg = c >> 5;            // 32 chunks per 512-K segment
        int kl  = (c & 31) << 4;     // x16 floats
        const float* sa = Asrc[seg];
        const float* sw = Bsrc[seg];
        #pragma unroll
        for (int i = 0; i < 2; i++) {
            int idx = i*256 + tid;
            int row = idx >> 2, q = idx & 3;
            cp16(aBuf + row*STRD2 + q*16, sa + ((size_t)row*Ss + s)*Ii + kl + q*4);
        }
        {
            int row = tid >> 2, q = tid & 3;
            cp16(bBuf + row*STRD2 + q*16, sw + (size_t)(n0 + row)*Ii + kl + q*4);
        }
    };

    float acc[2][4][4] = {};
    issue(0); issue(1); CP_COMMIT();
    issue(2); issue(3); CP_COMMIT();
    for (int p = 0; p < 48; p++) {
        if (p == 47) { CP_WAIT(0); } else { CP_WAIT(1); }
        __syncthreads();
        if (p + 2 < 48) { issue(2*p + 4); issue(2*p + 5); CP_COMMIT(); }
        uint32_t b0 = sb + ((2*p)     % NBUF2)*STAGE2;
        uint32_t b1 = sb + ((2*p + 1) % NBUF2)*STAGE2;
        compute_chunk_tf(b0, b0 + 128*STRD2, wm, wn, lane, acc);
        compute_chunk_tf(b1, b1 + 128*STRD2, wm, wn, lane, acc);
    }

    int quad = lane >> 2, tq = lane & 3;
    #pragma unroll
    for (int mt = 0; mt < 2; mt++) {
        #pragma unroll
        for (int nt = 0; nt < 4; nt++) {
            int row = wm + mt*16 + quad;
            int col = n0 + wn + nt*8 + tq*2;
            #pragma unroll
            for (int half = 0; half < 2; half++) {
                int rr = row + half*8;
                int m = s*Bb + rr;
                int id = g_idx[m];
                float v0 = acc[mt][nt][half*2+0] + wih[(size_t)col*IOio + Ii + id] + bih[col];
                float v1 = acc[mt][nt][half*2+1] + wih[(size_t)(col+1)*IOio + Ii + id] + bih[col+1];
                *(float2*)(g_gi + (size_t)m*Gg + col) = make_float2(v0, v1);
            }
        }
    }
}

// ============================================================
// 3) per-step hidden GEMM (bf16 6-product, split-K=3): R13 unchanged
// ============================================================
__global__ __launch_bounds__(256) void k_gemm_gh_mma() {
    extern __shared__ __align__(16) char dyn[];
    int tid = threadIdx.x, wid = tid >> 5, lane = tid & 31;
    int n0 = blockIdx.x * 64;
    int z  = blockIdx.y;
    int wm = (wid >> 1) * 32, wn = (wid & 1) * 32;
    uint32_t sb = smem_u32(dyn);
    const __nv_bfloat16* Ahs[3] = { g_h1, g_h2, g_h3 };
    const __nv_bfloat16* Bws[3] = { g_w1, g_w2, g_w3 };

    auto issue = [&](int c) {
        uint32_t aBuf = sb + (c % NBUF)*STAGE_BYTES;
        uint32_t bBuf = aBuf + 128*STRD;
        int cg  = z*64 + c;
        int seg = cg >> 5;
        int kl  = (cg & 31) << 5;
        const __nv_bfloat16* sa  = Ahs[SEG_A[seg]];
        const __nv_bfloat16* sbw = Bws[SEG_B[seg]];
        #pragma unroll
        for (int i = 0; i < 2; i++) {
            int idx = i*256 + tid;
            int row = idx >> 2, q = idx & 3;
            cp16(aBuf + row*STRD + q*16, sa + (size_t)row*Hh + kl + q*8);
        }
        {
            int row = tid >> 2, q = tid & 3;
            cp16(bBuf + row*STRD + q*16, sbw + (size_t)(n0 + row)*Hh + kl + q*8);
        }
    };

    float acc[2][4][4] = {};
    issue(0); issue(1); CP_COMMIT();
    issue(2); issue(3); CP_COMMIT();
    for (int p = 0; p < 32; p++) {
        if (p == 31) { CP_WAIT(0); } else { CP_WAIT(1); }
        __syncthreads();
        if (p + 2 < 32) { issue(2*p + 4); issue(2*p + 5); CP_COMMIT(); }
        uint32_t b0 = sb + ((2*p)     % NBUF)*STAGE_BYTES;
        uint32_t b1 = sb + ((2*p + 1) % NBUF)*STAGE_BYTES;
        compute_chunk(b0, b0 + 128*STRD, wm, wn, lane, acc);
        compute_chunk(b1, b1 + 128*STRD, wm, wn, lane, acc);
    }

    float* dst = g_ghp[z];
    int quad = lane >> 2, tq = lane & 3;
    #pragma unroll
    for (int mt = 0; mt < 2; mt++) {
        #pragma unroll
        for (int nt = 0; nt < 4; nt++) {
            int row = wm + mt*16 + quad;
            int col = n0 + wn + nt*8 + tq*2;
            *(float2*)(dst + (size_t)row*Gg + col)     = make_float2(acc[mt][nt][0], acc[mt][nt][1]);
            *(float2*)(dst + (size_t)(row+8)*Gg + col) = make_float2(acc[mt][nt][2], acc[mt][nt][3]);
        }
    }
}

// ============================================================
// 4) per-step GRU gate update (hy math bitwise R13; emits tf32 hs splits)
// ============================================================
__global__ __launch_bounds__(256) void k_update(int s, const float* __restrict__ bhh,
                                                float* __restrict__ out_pre) {
    int i4 = blockIdx.x * blockDim.x + threadIdx.x;
    if (i4 >= Bb*Hh/4) return;
    int i = i4 * 4;
    int b = i / Hh, hh = i % Hh;
    size_t gib = ((size_t)(s*Bb + b))*Gg + hh;
    float4 ir4 = __ldg((const float4*)(g_gi + gib));
    float4 iz4 = __ldg((const float4*)(g_gi + gib + Hh));
    float4 in4 = __ldg((const float4*)(g_gi + gib + 2*Hh));
    size_t ghb = (size_t)b*Gg + hh;
    float4 r0 = __ldcg((const float4*)(g_ghp[0] + ghb));
    float4 r1 = __ldcg((const float4*)(g_ghp[1] + ghb));
    float4 r2 = __ldcg((const float4*)(g_ghp[2] + ghb));
    float4 z0 = __ldcg((const float4*)(g_ghp[0] + ghb + Hh));
    float4 z1 = __ldcg((const float4*)(g_ghp[1] + ghb + Hh));
    float4 z2 = __ldcg((const float4*)(g_ghp[2] + ghb + Hh));
    float4 n0 = __ldcg((const float4*)(g_ghp[0] + ghb + 2*Hh));
    float4 n1 = __ldcg((const float4*)(g_ghp[1] + ghb + 2*Hh));
    float4 n2 = __ldcg((const float4*)(g_ghp[2] + ghb + 2*Hh));
    float4 br4 = __ldg((const float4*)(bhh + hh));
    float4 bz4 = __ldg((const float4*)(bhh + Hh + hh));
    float4 bn4 = __ldg((const float4*)(bhh + 2*Hh + hh));
    float4 h4  = *(const float4*)(g_h + i);

    float ir[4] = {ir4.x, ir4.y, ir4.z, ir4.w};
    float iz[4] = {iz4.x, iz4.y, iz4.z, iz4.w};
    float in_[4] = {in4.x, in4.y, in4.z, in4.w};
    float hr[4] = {(r0.x + r1.x) + r2.x + br4.x, (r0.y + r1.y) + r2.y + br4.y,
                   (r0.z + r1.z) + r2.z + br4.z, (r0.w + r1.w) + r2.w + br4.w};
    float hz[4] = {(z0.x + z1.x) + z2.x + bz4.x, (z0.y + z1.y) + z2.y + bz4.y,
                   (z0.z + z1.z) + z2.z + bz4.z, (z0.w + z1.w) + z2.w + bz4.w};
    float hn[4] = {(n0.x + n1.x) + n2.x + bn4.x, (n0.y + n1.y) + n2.y + bn4.y,
                   (n0.z + n1.z) + n2.z + bn4.z, (n0.w + n1.w) + n2.w + bn4.w};
    float hv[4] = {h4.x, h4.y, h4.z, h4.w};

    float hy[4], pre[4];
    __nv_bfloat16 s1[4], s2[4], s3[4];
    float ta[4], tb[4];
    #pragma unroll
    for (int j = 0; j < 4; j++) {
        float r  = 1.0f/(1.0f + expf(-(ir[j]+hr[j])));
        float zz = 1.0f/(1.0f + expf(-(iz[j]+hz[j])));
        pre[j] = in_[j] + r*hn[j];
        float n = tanhf(pre[j]);
        hy[j] = n + zz*(hv[j] - n);
        split3(hy[j], s1[j], s2[j], s3[j]);
        ta[j] = tf32_rna(hy[j]);
        tb[j] = tf32_rna(hy[j] - ta[j]);
    }
    *(float4*)(g_h + i) = make_float4(hy[0], hy[1], hy[2], hy[3]);
    #pragma unroll
    for (int j = 0; j < 4; j++) { g_h1[i+j] = s1[j]; g_h2[i+j] = s2[j]; g_h3[i+j] = s3[j]; }
    size_t om = ((size_t)b*Ss + s)*Hh + hh;
    *(float4*)(g_hsa + om) = make_float4(ta[0], ta[1], ta[2], ta[3]);
    *(float4*)(g_hsb + om) = make_float4(tb[0], tb[1], tb[2], tb[3]);
    *(float4*)(out_pre + om) = make_float4(pre[0], pre[1], pre[2], pre[3]);
}

// ============================================================
// 5) output head GEMM via tf32 3-product: M=32768, N=512, K'=3x1024
//    grid (8, 256); 192 chunks of BK=16; paired pipeline.
// ============================================================
__global__ __launch_bounds__(256) void k_gemm_logits_tf(const float* __restrict__ lb) {
    extern __shared__ __align__(16) char dyn[];
    int tid = threadIdx.x, wid = tid >> 5, lane = tid & 31;
    int n0 = blockIdx.x * 64;
    int m0 = blockIdx.y * 128;
    int wm = (wid >> 1) * 32, wn = (wid & 1) * 32;
    uint32_t sb = smem_u32(dyn);
    const float* Asrc[3] = { g_hsa, g_hsb, g_hsa };
    const float* Bsrc[3] = { g_lwb, g_lwa, g_lwa };

    auto issue = [&](int c) {
        uint32_t aBuf = sb + (c % NBUF2)*STAGE2;
        uint32_t bBuf = aBuf + 128*STRD2;
        int seg = c >> 6;            // 64 chunks per 1024-K segment
        int kl  = (c & 63) << 4;
        const float* sa = Asrc[seg];
        const float* sw = Bsrc[seg];
        #pragma unroll
        for (int i = 0; i < 2; i++) {
            int idx = i*256 + tid;
            int row = idx >> 2, q = idx & 3;
            cp16(aBuf + row*STRD2 + q*16, sa + (size_t)(m0 + row)*Hh + kl + q*4);
        }
        {
            int row = tid >> 2, q = tid & 3;
            cp16(bBuf + row*STRD2 + q*16, sw + (size_t)(n0 + row)*Hh + kl + q*4);
        }
    };

    float acc[2][4][4] = {};
    issue(0); issue(1); CP_COMMIT();
    issue(2); issue(3); CP_COMMIT();
    for (int p = 0; p < 96; p++) {
        if (p == 95) { CP_WAIT(0); } else { CP_WAIT(1); }
        __syncthreads();
        if (p + 2 < 96) { issue(2*p + 4); issue(2*p + 5); CP_COMMIT(); }
        uint32_t b0 = sb + ((2*p)     % NBUF2)*STAGE2;
        uint32_t b1 = sb + ((2*p + 1) % NBUF2)*STAGE2;
        compute_chunk_tf(b0, b0 + 128*STRD2, wm, wn, lane, acc);
        compute_chunk_tf(b1, b1 + 128*STRD2, wm, wn, lane, acc);
    }

    int quad = lane >> 2, tq = lane & 3;
    #pragma unroll
    for (int mt = 0; mt < 2; mt++) {
        #pragma unroll
        for (int nt = 0; nt < 4; nt++) {
            int row = wm + mt*16 + quad;
            int col = n0 + wn + nt*8 + tq*2;
            float2 v0 = make_float2(acc[mt][nt][0] + lb[col], acc[mt][nt][1] + lb[col+1]);
            float2 v1 = make_float2(acc[mt][nt][2] + lb[col], acc[mt][nt][3] + lb[col+1]);
            *(float2*)(g_logits + (size_t)(m0+row)*Oo + col)   = v0;
            *(float2*)(g_logits + (size_t)(m0+row+8)*Oo + col) = v1;
        }
    }
}

// ============================================================
// 6) softmax + argmax one-hot (identical to R5)
// ============================================================
__global__ __launch_bounds__(128) void k_softmax(float* __restrict__ out) {
    int m = blockIdx.x;
    const float* lg = g_logits + (size_t)m*Oo;
    __shared__ float smax[128];
    __shared__ int   sidx[128];
    __shared__ float ssum[128];
    int t = threadIdx.x;
    float vmax = -1e30f; int vidx = 0;
    for (int o = t; o < Oo; o += 128) {
        float v = lg[o];
        if (v > vmax) { vmax = v; vidx = o; }
    }
    smax[t] = vmax; sidx[t] = vidx; __syncthreads();
    for (int off = 64; off; off >>= 1) {
        if (t < off) {
            if (smax[t+off] > smax[t] || (smax[t+off] == smax[t] && sidx[t+off] < sidx[t])) {
                smax[t] = smax[t+off]; sidx[t] = sidx[t+off];
            }
        }
        __syncthreads();
    }
    float rmax = smax[0]; int amax = sidx[0];
    float lsum = 0.f;
    for (int o = t; o < Oo; o += 128) lsum += expf(lg[o]-rmax);
    ssum[t] = lsum; __syncthreads();
    for (int off = 64; off; off >>= 1) {
        if (t < off) ssum[t] += ssum[t+off];
        __syncthreads();
    }
    float inv = 1.0f / ssum[0];
    float* probs = out + PROBS_OFF + (size_t)m*Oo;
    float* samp  = out + SAMP_OFF  + (size_t)m*Oo;
    for (int o = t; o < Oo; o += 128) {
        probs[o] = expf(lg[o]-rmax) * inv;
        samp[o]  = (o == amax) ? 1.0f : 0.0f;
    }
}

__global__ void k_hx(float* __restrict__ out) {
    int i = blockIdx.x * blockDim.x + threadIdx.x;
    if (i < Bb*Hh) out[i] = g_h[i];
}

// ============================================================
extern "C" void kernel_launch(void* const* d_in, const int* in_sizes, int n_in,
                              void* d_out, int out_size) {
    const float* y   = (const float*)d_in[0];
    const float* gt  = (const float*)d_in[1];
    const float* hx  = (const float*)d_in[2];
    const float* wih = (const float*)d_in[3];
    const float* bih = (const float*)d_in[4];
    const float* whh = (const float*)d_in[5];
    const float* bhh = (const float*)d_in[6];
    const float* lw  = (const float*)d_in[7];
    const float* lb  = (const float*)d_in[8];
    const float* got = (const float*)d_in[9];
    float* out = (float*)d_out;

    cudaFuncSetAttribute(k_gemm_gh_mma, cudaFuncAttributeMaxDynamicSharedMemorySize,
                         NBUF*STAGE_BYTES);
    cudaFuncSetAttribute(k_gemm_gi_tf, cudaFuncAttributeMaxDynamicSharedMemorySize,
                         NBUF2*STAGE2);
    cudaFuncSetAttribute(k_gemm_logits_tf, cudaFuncAttributeMaxDynamicSharedMemorySize,
                         NBUF2*STAGE2);

    k_idx<<<(Bb*Ss)/8, 256>>>(gt, got);
    k_split_w<<<(Gg*Hh)/256, 256>>>(whh);
    k_copyh<<<(Bb*Hh)/256, 256>>>(hx);
    k_split2_y<<<(Bb*Ss*Ii)/256, 256>>>(y);
    k_split2_wiy<<<(Gg*Ii)/256, 256>>>(wih);
    k_split2_lw<<<(Oo*Hh)/256, 256>>>(lw);
    k_gemm_gi_tf<<<dim3(Gg/64, Ss), 256, NBUF2*STAGE2>>>(wih, bih);
    for (int s = 0; s < Ss; s++) {
        k_gemm_gh_mma<<<dim3(Gg/64, 3), 256, NBUF*STAGE_BYTES>>>();
        k_update<<<(Bb*Hh/4)/256, 256>>>(s, bhh, out + PRE_OFF);
    }
    k_gemm_logits_tf<<<dim3(Oo/64, (Bb*Ss)/128), 256, NBUF2*STAGE2>>>(lb);
    k_softmax<<<Bb*Ss, 128>>>(out);
    k_hx<<<(Bb*Hh+255)/256, 256>>>(out + HX_OFF);
}

// round 16
// speedup vs baseline: 1.0422x; 1.0422x over previous
#include <cuda_runtime.h>
#include <cuda_bf16.h>
#include <math.h>
#include <stdint.h>

#define Bb 128
#define Ss 256
#define Ii 512
#define Oo 512
#define Hh 1024
#define Gg (3*Hh)      // 3072
#define IOio (Ii+Oo)   // 1024

// ---- output layout ----
#define PROBS_OFF  0
#define PRE_OFF    ((size_t)Bb*Ss*Oo)
#define SAMP_OFF   (PRE_OFF + (size_t)Bb*Ss*Hh)
#define HX_OFF     (SAMP_OFF + (size_t)Bb*Ss*Oo)

// ---- scratch ----
__device__ int   g_idx[Bb*Ss];
__device__ float g_gi[(size_t)Ss*Bb*Gg];
__device__ float g_h[Bb*Hh];
__device__ float g_ghp[3][(size_t)Bb*Gg];
__device__ float g_hs[(size_t)Bb*Ss*Hh];
__device__ float g_logits[(size_t)Bb*Ss*Oo];
// bf16 3-way splits (recurrence)
__device__ __nv_bfloat16 g_h1[Bb*Hh];
__device__ __nv_bfloat16 g_h2[Bb*Hh];
__device__ __nv_bfloat16 g_h3[Bb*Hh];
__device__ __nv_bfloat16 g_w1[(size_t)Gg*Hh];
__device__ __nv_bfloat16 g_w2[(size_t)Gg*Hh];
__device__ __nv_bfloat16 g_w3[(size_t)Gg*Hh];
// bf16 3-way splits for gi GEMM (y and wih y-part)
__device__ __nv_bfloat16 g_q1[(size_t)Bb*Ss*Ii];
__device__ __nv_bfloat16 g_q2[(size_t)Bb*Ss*Ii];
__device__ __nv_bfloat16 g_q3[(size_t)Bb*Ss*Ii];
__device__ __nv_bfloat16 g_u1[(size_t)Gg*Ii];
__device__ __nv_bfloat16 g_u2[(size_t)Gg*Ii];
__device__ __nv_bfloat16 g_u3[(size_t)Gg*Ii];

// recurrence product table (R5 order, bitwise-preserved)
__constant__ int SEG_A[6] = {0,0,1,0,2,1};
__constant__ int SEG_B[6] = {0,1,0,2,0,1};
// gi product table: SMALL products first -> large last (accumulation noise fix)
// (y2w2), (y3w1), (y1w3), (y2w1), (y1w2), (y1w1)
__constant__ int GSEG_A[6] = {1,2,0,1,0,0};
__constant__ int GSEG_B[6] = {1,0,2,0,1,0};

// ============================================================
// PTX helpers
// ============================================================
__device__ __forceinline__ uint32_t smem_u32(const void* p) {
    uint32_t a;
    asm("{ .reg .u64 t; cvta.to.shared.u64 t, %1; cvt.u32.u64 %0, t; }" : "=r"(a) : "l"(p));
    return a;
}
__device__ __forceinline__ void cp16(uint32_t dst, const void* src) {
    asm volatile("cp.async.cg.shared.global [%0], [%1], 16;" :: "r"(dst), "l"(src));
}
#define CP_COMMIT() asm volatile("cp.async.commit_group;" ::: "memory")
#define CP_WAIT(n)  asm volatile("cp.async.wait_group %0;" :: "n"(n) : "memory")

__device__ __forceinline__ void ldmA(uint32_t* a, uint32_t addr) {
    asm volatile("ldmatrix.sync.aligned.m8n8.x4.shared.b16 {%0,%1,%2,%3}, [%4];"
        : "=r"(a[0]), "=r"(a[1]), "=r"(a[2]), "=r"(a[3]) : "r"(addr));
}
__device__ __forceinline__ void ldmB4(uint32_t* b, uint32_t addr) {
    asm volatile("ldmatrix.sync.aligned.m8n8.x4.shared.b16 {%0,%1,%2,%3}, [%4];"
        : "=r"(b[0]), "=r"(b[1]), "=r"(b[2]), "=r"(b[3]) : "r"(addr));
}
__device__ __forceinline__ void mma_bf16(float* c, const uint32_t* a, const uint32_t* b) {
    asm volatile("mma.sync.aligned.m16n8k16.row.col.f32.bf16.bf16.f32 "
        "{%0,%1,%2,%3}, {%4,%5,%6,%7}, {%8,%9}, {%0,%1,%2,%3};"
        : "+f"(c[0]), "+f"(c[1]), "+f"(c[2]), "+f"(c[3])
        : "r"(a[0]), "r"(a[1]), "r"(a[2]), "r"(a[3]), "r"(b[0]), "r"(b[1]));
}

#define STRD 80                      // smem row stride (64B data + 16B pad)
#define STAGE_BYTES ((128+64)*STRD)  // 15360 per chunk buffer
#define NBUF 6                       // 3 pairs x 2 chunks

// One BK=32 chunk, warp tile 32(M) x 32(N); 8 warps = 4M x 2N over 128x64.
__device__ __forceinline__ void compute_chunk(uint32_t aB, uint32_t bB, int wm, int wn,
                                              int lane, float acc[2][4][4]) {
    uint32_t a[2][2][4], b[2][2][4];
    int t = lane >> 3, r = lane & 7;
    #pragma unroll
    for (int kk = 0; kk < 2; kk++) {
        #pragma unroll
        for (int mt = 0; mt < 2; mt++)
            ldmA(a[kk][mt], aB + (wm + mt*16 + (lane & 15))*STRD + kk*32 + ((lane >> 4) & 1)*16);
        #pragma unroll
        for (int ldi = 0; ldi < 2; ldi++)
            ldmB4(b[kk][ldi], bB + (wn + ldi*16 + (t >> 1)*8 + r)*STRD + kk*32 + (t & 1)*16);
    }
    #pragma unroll
    for (int kk = 0; kk < 2; kk++)
        #pragma unroll
        for (int mt = 0; mt < 2; mt++)
            #pragma unroll
            for (int nt = 0; nt < 4; nt++)
                mma_bf16(acc[mt][nt], a[kk][mt], &b[kk][nt >> 1][(nt & 1)*2]);
}

// ============================================================
// prep kernels
// ============================================================
__global__ void k_idx(const float* __restrict__ gt, const float* __restrict__ gotoken) {
    int wg   = (blockIdx.x * blockDim.x + threadIdx.x) >> 5;
    int lane = threadIdx.x & 31;
    if (wg >= Bb*Ss) return;
    int s = wg / Bb, b = wg % Bb;
    const float* src = (s == 0) ? gotoken : (gt + ((size_t)b*Ss + (s-1))*Oo);
    int found = Oo;
    for (int o = lane; o < Oo; o += 32)
        if (src[o] > 0.5f) found = min(found, o);
    #pragma unroll
    for (int off = 16; off; off >>= 1)
        found = min(found, __shfl_xor_sync(0xffffffffu, found, off));
    if (lane == 0) g_idx[wg] = found;
}

__device__ __forceinline__ void split3(float v, __nv_bfloat16& a, __nv_bfloat16& b, __nv_bfloat16& c) {
    a = __float2bfloat16(v);
    float r = v - __bfloat162float(a);
    b = __float2bfloat16(r);
    c = __float2bfloat16(r - __bfloat162float(b));
}

__global__ void k_copyh(const float* __restrict__ hx) {
    int i = blockIdx.x * blockDim.x + threadIdx.x;
    if (i < Bb*Hh) {
        float v = hx[i];
        g_h[i] = v;
        split3(v, g_h1[i], g_h2[i], g_h3[i]);
    }
}
__global__ void k_split_w(const float* __restrict__ w) {
    int i = blockIdx.x * blockDim.x + threadIdx.x;
    if (i < Gg*Hh) split3(w[i], g_w1[i], g_w2[i], g_w3[i]);
}
__global__ void k_split_y(const float* __restrict__ y) {
    int i = blockIdx.x * blockDim.x + threadIdx.x;
    if (i < Bb*Ss*Ii) split3(y[i], g_q1[i], g_q2[i], g_q3[i]);
}
__global__ void k_split_wih(const float* __restrict__ wih) {
    int i = blockIdx.x * blockDim.x + threadIdx.x;
    if (i < Gg*Ii) {
        int row = i / Ii, col = i % Ii;
        split3(wih[(size_t)row*IOio + col], g_u1[i], g_u2[i], g_u3[i]);
    }
}

// ============================================================
// 2) gi GEMM via bf16 6-product (small products FIRST), R13 step-GEMM
//    machinery. Per-s tile 128x3072, K'=6x512 -> 96 chunks of BK=32.
//    grid (48, 256); paired pipeline; epilogue adds one-hot gather + bias.
// ============================================================
__global__ __launch_bounds__(256) void k_gemm_gi_bf(const float* __restrict__ wih,
                                                    const float* __restrict__ bih) {
    extern __shared__ __align__(16) char dyn[];
    int tid = threadIdx.x, wid = tid >> 5, lane = tid & 31;
    int n0 = blockIdx.x * 64;
    int s  = blockIdx.y;
    int wm = (wid >> 1) * 32, wn = (wid & 1) * 32;
    uint32_t sb = smem_u32(dyn);
    const __nv_bfloat16* Qs[3] = { g_q1, g_q2, g_q3 };
    const __nv_bfloat16* Us[3] = { g_u1, g_u2, g_u3 };

    auto issue = [&](int c) {
        uint32_t aBuf = sb + (c % NBUF)*STAGE_BYTES;
        uint32_t bBuf = aBuf + 128*STRD;
        int seg = c >> 4;               // 16 chunks per 512-K segment
        int kl  = (c & 15) << 5;
        const __nv_bfloat16* sa = Qs[GSEG_A[seg]];
        const __nv_bfloat16* sw = Us[GSEG_B[seg]];
        #pragma unroll
        for (int i = 0; i < 2; i++) {
            int idx = i*256 + tid;
            int row = idx >> 2, q = idx & 3;
            cp16(aBuf + row*STRD + q*16, sa + ((size_t)row*Ss + s)*Ii + kl + q*8);
        }
        {
            int row = tid >> 2, q = tid & 3;
            cp16(bBuf + row*STRD + q*16, sw + (size_t)(n0 + row)*Ii + kl + q*8);
        }
    };

    float acc[2][4][4] = {};
    issue(0); issue(1); CP_COMMIT();
    issue(2); issue(3); CP_COMMIT();
    for (int p = 0; p < 48; p++) {
        if (p == 47) { CP_WAIT(0); } else { CP_WAIT(1); }
        __syncthreads();
        if (p + 2 < 48) { issue(2*p + 4); issue(2*p + 5); CP_COMMIT(); }
        uint32_t b0 = sb + ((2*p)     % NBUF)*STAGE_BYTES;
        uint32_t b1 = sb + ((2*p + 1) % NBUF)*STAGE_BYTES;
        compute_chunk(b0, b0 + 128*STRD, wm, wn, lane, acc);
        compute_chunk(b1, b1 + 128*STRD, wm, wn, lane, acc);
    }

    int quad = lane >> 2, tq = lane & 3;
    #pragma unroll
    for (int mt = 0; mt < 2; mt++) {
        #pragma unroll
        for (int nt = 0; nt < 4; nt++) {
            int row = wm + mt*16 + quad;
            int col = n0 + wn + nt*8 + tq*2;
            #pragma unroll
            for (int half = 0; half < 2; half++) {
                int rr = row + half*8;
                int m = s*Bb + rr;
                int id = g_idx[m];
                float v0 = acc[mt][nt][half*2+0] + wih[(size_t)col*IOio + Ii + id] + bih[col];
                float v1 = acc[mt][nt][half*2+1] + wih[(size_t)(col+1)*IOio + Ii + id] + bih[col+1];
                *(float2*)(g_gi + (size_t)m*Gg + col) = make_float2(v0, v1);
            }
        }
    }
}

// ============================================================
// 3) per-step hidden GEMM (bf16 6-product, split-K=3): R13 unchanged
// ============================================================
__global__ __launch_bounds__(256) void k_gemm_gh_mma() {
    extern __shared__ __align__(16) char dyn[];
    int tid = threadIdx.x, wid = tid >> 5, lane = tid & 31;
    int n0 = blockIdx.x * 64;
    int z  = blockIdx.y;
    int wm = (wid >> 1) * 32, wn = (wid & 1) * 32;
    uint32_t sb = smem_u32(dyn);
    const __nv_bfloat16* Ahs[3] = { g_h1, g_h2, g_h3 };
    const __nv_bfloat16* Bws[3] = { g_w1, g_w2, g_w3 };

    auto issue = [&](int c) {
        uint32_t aBuf = sb + (c % NBUF)*STAGE_BYTES;
        uint32_t bBuf = aBuf + 128*STRD;
        int cg  = z*64 + c;
        int seg = cg >> 5;
        int kl  = (cg & 31) << 5;
        const __nv_bfloat16* sa  = Ahs[SEG_A[seg]];
        const __nv_bfloat16* sbw = Bws[SEG_B[seg]];
        #pragma unroll
        for (int i = 0; i < 2; i++) {
            int idx = i*256 + tid;
            int row = idx >> 2, q = idx & 3;
            cp16(aBuf + row*STRD + q*16, sa + (size_t)row*Hh + kl + q*8);
        }
        {
            int row = tid >> 2, q = tid & 3;
            cp16(bBuf + row*STRD + q*16, sbw + (size_t)(n0 + row)*Hh + kl + q*8);
        }
    };

    float acc[2][4][4] = {};
    issue(0); issue(1); CP_COMMIT();
    issue(2); issue(3); CP_COMMIT();
    for (int p = 0; p < 32; p++) {
        if (p == 31) { CP_WAIT(0); } else { CP_WAIT(1); }
        __syncthreads();
        if (p + 2 < 32) { issue(2*p + 4); issue(2*p + 5); CP_COMMIT(); }
        uint32_t b0 = sb + ((2*p)     % NBUF)*STAGE_BYTES;
        uint32_t b1 = sb + ((2*p + 1) % NBUF)*STAGE_BYTES;
        compute_chunk(b0, b0 + 128*STRD, wm, wn, lane, acc);
        compute_chunk(b1, b1 + 128*STRD, wm, wn, lane, acc);
    }

    float* dst = g_ghp[z];
    int quad = lane >> 2, tq = lane & 3;
    #pragma unroll
    for (int mt = 0; mt < 2; mt++) {
        #pragma unroll
        for (int nt = 0; nt < 4; nt++) {
            int row = wm + mt*16 + quad;
            int col = n0 + wn + nt*8 + tq*2;
            *(float2*)(dst + (size_t)row*Gg + col)     = make_float2(acc[mt][nt][0], acc[mt][nt][1]);
            *(float2*)(dst + (size_t)(row+8)*Gg + col) = make_float2(acc[mt][nt][2], acc[mt][nt][3]);
        }
    }
}

// ============================================================
// 4) per-step GRU gate update (float4 vectorized; identical to R13)
// ============================================================
__global__ __launch_bounds__(256) void k_update(int s, const float* __restrict__ bhh,
                                                float* __restrict__ out_pre) {
    int i4 = blockIdx.x * blockDim.x + threadIdx.x;
    if (i4 >= Bb*Hh/4) return;
    int i = i4 * 4;
    int b = i / Hh, hh = i % Hh;
    size_t gib = ((size_t)(s*Bb + b))*Gg + hh;
    float4 ir4 = __ldg((const float4*)(g_gi + gib));
    float4 iz4 = __ldg((const float4*)(g_gi + gib + Hh));
    float4 in4 = __ldg((const float4*)(g_gi + gib + 2*Hh));
    size_t ghb = (size_t)b*Gg + hh;
    float4 r0 = __ldcg((const float4*)(g_ghp[0] + ghb));
    float4 r1 = __ldcg((const float4*)(g_ghp[1] + ghb));
    float4 r2 = __ldcg((const float4*)(g_ghp[2] + ghb));
    float4 z0 = __ldcg((const float4*)(g_ghp[0] + ghb + Hh));
    float4 z1 = __ldcg((const float4*)(g_ghp[1] + ghb + Hh));
    float4 z2 = __ldcg((const float4*)(g_ghp[2] + ghb + Hh));
    float4 n0 = __ldcg((const float4*)(g_ghp[0] + ghb + 2*Hh));
    float4 n1 = __ldcg((const float4*)(g_ghp[1] + ghb + 2*Hh));
    float4 n2 = __ldcg((const float4*)(g_ghp[2] + ghb + 2*Hh));
    float4 br4 = __ldg((const float4*)(bhh + hh));
    float4 bz4 = __ldg((const float4*)(bhh + Hh + hh));
    float4 bn4 = __ldg((const float4*)(bhh + 2*Hh + hh));
    float4 h4  = *(const float4*)(g_h + i);

    float ir[4] = {ir4.x, ir4.y, ir4.z, ir4.w};
    float iz[4] = {iz4.x, iz4.y, iz4.z, iz4.w};
    float in_[4] = {in4.x, in4.y, in4.z, in4.w};
    float hr[4] = {(r0.x + r1.x) + r2.x + br4.x, (r0.y + r1.y) + r2.y + br4.y,
                   (r0.z + r1.z) + r2.z + br4.z, (r0.w + r1.w) + r2.w + br4.w};
    float hz[4] = {(z0.x + z1.x) + z2.x + bz4.x, (z0.y + z1.y) + z2.y + bz4.y,
                   (z0.z + z1.z) + z2.z + bz4.z, (z0.w + z1.w) + z2.w + bz4.w};
    float hn[4] = {(n0.x + n1.x) + n2.x + bn4.x, (n0.y + n1.y) + n2.y + bn4.y,
                   (n0.z + n1.z) + n2.z + bn4.z, (n0.w + n1.w) + n2.w + bn4.w};
    float hv[4] = {h4.x, h4.y, h4.z, h4.w};

    float hy[4], pre[4];
    __nv_bfloat16 s1[4], s2[4], s3[4];
    #pragma unroll
    for (int j = 0; j < 4; j++) {
        float r  = 1.0f/(1.0f + expf(-(ir[j]+hr[j])));
        float zz = 1.0f/(1.0f + expf(-(iz[j]+hz[j])));
        pre[j] = in_[j] + r*hn[j];
        float n = tanhf(pre[j]);
        hy[j] = n + zz*(hv[j] - n);
        split3(hy[j], s1[j], s2[j], s3[j]);
    }
    *(float4*)(g_h + i) = make_float4(hy[0], hy[1], hy[2], hy[3]);
    #pragma unroll
    for (int j = 0; j < 4; j++) { g_h1[i+j] = s1[j]; g_h2[i+j] = s2[j]; g_h3[i+j] = s3[j]; }
    size_t om = ((size_t)b*Ss + s)*Hh + hh;
    *(float4*)(g_hs + om)   = make_float4(hy[0], hy[1], hy[2], hy[3]);
    *(float4*)(out_pre + om) = make_float4(pre[0], pre[1], pre[2], pre[3]);
}

// ============================================================
// 5) output head GEMM (fp32, 128x64 tile, reg-prefetch; identical to R13)
// ============================================================
__global__ __launch_bounds__(256) void k_gemm_logits(const float* __restrict__ lw,
                                                     const float* __restrict__ lb) {
    __shared__ float As[16][128+4];
    __shared__ float Bs[16][64+4];
    int m0 = blockIdx.y * 128;
    int n0 = blockIdx.x * 64;
    int tid = threadIdx.x;
    int tx = tid & 15, ty = tid >> 4;
    float acc[8][4] = {};
    int arow = tid >> 2;
    int acol = (tid & 3) * 4;

    float4 pa[2], pb;
    #pragma unroll
    for (int hseg = 0; hseg < 2; hseg++)
        pa[hseg] = *(const float4*)(g_hs + (size_t)(m0 + arow + hseg*64)*Hh + acol);
    pb = *(const float4*)(lw + (size_t)(n0 + arow)*Hh + acol);

    for (int k0 = 0; k0 < Hh; k0 += 16) {
        #pragma unroll
        for (int hseg = 0; hseg < 2; hseg++) {
            int r = arow + hseg*64;
            As[acol+0][r] = pa[hseg].x; As[acol+1][r] = pa[hseg].y;
            As[acol+2][r] = pa[hseg].z; As[acol+3][r] = pa[hseg].w;
        }
        Bs[acol+0][arow] = pb.x; Bs[acol+1][arow] = pb.y;
        Bs[acol+2][arow] = pb.z; Bs[acol+3][arow] = pb.w;
        __syncthreads();
        if (k0 + 16 < Hh) {
            #pragma unroll
            for (int hseg = 0; hseg < 2; hseg++)
                pa[hseg] = *(const float4*)(g_hs + (size_t)(m0 + arow + hseg*64)*Hh + k0 + 16 + acol);
            pb = *(const float4*)(lw + (size_t)(n0 + arow)*Hh + k0 + 16 + acol);
        }
        #pragma unroll
        for (int k = 0; k < 16; k++) {
            float ar[8], br[4];
            #pragma unroll
            for (int i2 = 0; i2 < 8; i2++) ar[i2] = As[k][ty*8+i2];
            #pragma unroll
            for (int j = 0; j < 4; j++)   br[j]  = Bs[k][tx*4+j];
            #pragma unroll
            for (int i2 = 0; i2 < 8; i2++)
                #pragma unroll
                for (int j = 0; j < 4; j++) acc[i2][j] += ar[i2]*br[j];
        }
        __syncthreads();
    }
    #pragma unroll
    for (int i2 = 0; i2 < 8; i2++) {
        int m = m0 + ty*8 + i2;
        #pragma unroll
        for (int j = 0; j < 4; j++) {
            int oo = n0 + tx*4 + j;
            g_logits[(size_t)m*Oo + oo] = acc[i2][j] + lb[oo];
        }
    }
}

// ============================================================
// 6) softmax + argmax one-hot (identical to R5)
// ============================================================
__global__ __launch_bounds__(128) void k_softmax(float* __restrict__ out) {
    int m = blockIdx.x;
    const float* lg = g_logits + (size_t)m*Oo;
    __shared__ float smax[128];
    __shared__ int   sidx[128];
    __shared__ float ssum[128];
    int t = threadIdx.x;
    float vmax = -1e30f; int vidx = 0;
    for (int o = t; o < Oo; o += 128) {
        float v = lg[o];
        if (v > vmax) { vmax = v; vidx = o; }
    }
    smax[t] = vmax; sidx[t] = vidx; __syncthreads();
    for (int off = 64; off; off >>= 1) {
        if (t < off) {
            if (smax[t+off] > smax[t] || (smax[t+off] == smax[t] && sidx[t+off] < sidx[t])) {
                smax[t] = smax[t+off]; sidx[t] = sidx[t+off];
            }
        }
        __syncthreads();
    }
    float rmax = smax[0]; int amax = sidx[0];
    float lsum = 0.f;
    for (int o = t; o < Oo; o += 128) lsum += expf(lg[o]-rmax);
    ssum[t] = lsum; __syncthreads();
    for (int off = 64; off; off >>= 1) {
        if (t < off) ssum[t] += ssum[t+off];
        __syncthreads();
    }
    float inv = 1.0f / ssum[0];
    float* probs = out + PROBS_OFF + (size_t)m*Oo;
    float* samp  = out + SAMP_OFF  + (size_t)m*Oo;
    for (int o = t; o < Oo; o += 128) {
        probs[o] = expf(lg[o]-rmax) * inv;
        samp[o]  = (o == amax) ? 1.0f : 0.0f;
    }
}

__global__ void k_hx(float* __restrict__ out) {
    int i = blockIdx.x * blockDim.x + threadIdx.x;
    if (i < Bb*Hh) out[i] = g_h[i];
}

// ============================================================
extern "C" void kernel_launch(void* const* d_in, const int* in_sizes, int n_in,
                              void* d_out, int out_size) {
    const float* y   = (const float*)d_in[0];
    const float* gt  = (const float*)d_in[1];
    const float* hx  = (const float*)d_in[2];
    const float* wih = (const float*)d_in[3];
    const float* bih = (const float*)d_in[4];
    const float* whh = (const float*)d_in[5];
    const float* bhh = (const float*)d_in[6];
    const float* lw  = (const float*)d_in[7];
    const float* lb  = (const float*)d_in[8];
    const float* got = (const float*)d_in[9];
    float* out = (float*)d_out;

    cudaFuncSetAttribute(k_gemm_gh_mma, cudaFuncAttributeMaxDynamicSharedMemorySize,
                         NBUF*STAGE_BYTES);
    cudaFuncSetAttribute(k_gemm_gi_bf, cudaFuncAttributeMaxDynamicSharedMemorySize,
                         NBUF*STAGE_BYTES);

    k_idx<<<(Bb*Ss)/8, 256>>>(gt, got);
    k_split_w<<<(Gg*Hh)/256, 256>>>(whh);
    k_copyh<<<(Bb*Hh)/256, 256>>>(hx);
    k_split_y<<<(Bb*Ss*Ii)/256, 256>>>(y);
    k_split_wih<<<(Gg*Ii)/256, 256>>>(wih);
    k_gemm_gi_bf<<<dim3(Gg/64, Ss), 256, NBUF*STAGE_BYTES>>>(wih, bih);
    for (int s = 0; s < Ss; s++) {
        k_gemm_gh_mma<<<dim3(Gg/64, 3), 256, NBUF*STAGE_BYTES>>>();
        k_update<<<(Bb*Hh/4)/256, 256>>>(s, bhh, out + PRE_OFF);
    }
    k_gemm_logits<<<dim3(Oo/64, (Bb*Ss)/128), 256>>>(lw, lb);
    k_softmax<<<Bb*Ss, 128>>>(out);
    k_hx<<<(Bb*Hh+255)/256, 256>>>(out + HX_OFF);
}